// round 1
// baseline (speedup 1.0000x reference)
#include <cuda_runtime.h>
#include <cstdint>

#define NU 100000
#define NG 20000
#define NE 1000000
#define NS 500000
#define HH 256

// ----------------------------------------------------------------------------
// Static device scratch (no runtime allocation allowed)
// ----------------------------------------------------------------------------
__device__ float d_xg[NG * 128];          // concat(x_game, emb_game)
__device__ float d_u0[(size_t)NU * HH];
__device__ float d_u1[(size_t)NU * HH];
__device__ float d_g0[NG * HH];
__device__ float d_g1[NG * HH];
__device__ float d_msg_g[NG * HH];
__device__ float d_y[NG * HH];
__device__ float d_msg_u[(size_t)NU * HH];

__device__ int   d_rp_ug[NG + 1];
__device__ int   d_rp_gu[NU + 1];
__device__ int   d_cur_ug[NG + 1];
__device__ int   d_cur_gu[NU + 1];
__device__ int   d_es_ug[NE];
__device__ float d_ws_ug[NE];
__device__ int   d_es_gu[NE];
__device__ float d_ws_gu[NE];

// ----------------------------------------------------------------------------
// Setup kernels
// ----------------------------------------------------------------------------
__global__ void k_concat(const float* __restrict__ xg64, const float* __restrict__ emb) {
    int i = blockIdx.x * blockDim.x + threadIdx.x;   // over NG*64
    if (i < NG * 64) {
        int r = i >> 6, c = i & 63;
        d_xg[r * 128 + c]      = xg64[i];
        d_xg[r * 128 + 64 + c] = emb[i];
    }
}

__global__ void k_zero_counts() {
    int i = blockIdx.x * blockDim.x + threadIdx.x;
    if (i <= NG) d_cur_ug[i] = 0;
    if (i <= NU) d_cur_gu[i] = 0;
}

__global__ void k_hist(const int* __restrict__ dug, const int* __restrict__ dgu) {
    int e = blockIdx.x * blockDim.x + threadIdx.x;
    if (e < NE) {
        atomicAdd(&d_cur_ug[dug[e]], 1);
        atomicAdd(&d_cur_gu[dgu[e]], 1);
    }
}

// Exclusive scan: block 0 scans games counts, block 1 scans users counts.
__global__ void k_scan() {
    int n; int* cnt; int* rp;
    if (blockIdx.x == 0) { n = NG; cnt = d_cur_ug; rp = d_rp_ug; }
    else                 { n = NU; cnt = d_cur_gu; rp = d_rp_gu; }
    __shared__ int s[1024];
    int tid = threadIdx.x;
    int carry = 0;
    for (int base = 0; base < n; base += 1024) {
        int x = (base + tid < n) ? cnt[base + tid] : 0;
        s[tid] = x;
        __syncthreads();
        for (int off = 1; off < 1024; off <<= 1) {
            int v = (tid >= off) ? s[tid - off] : 0;
            __syncthreads();
            s[tid] += v;
            __syncthreads();
        }
        if (base + tid < n) rp[base + tid] = carry + s[tid] - x;
        int tot = s[1023];
        __syncthreads();
        carry += tot;
    }
    if (tid == 0) rp[n] = carry;
}

__global__ void k_cursor() {
    int i = blockIdx.x * blockDim.x + threadIdx.x;
    if (i <= NG) d_cur_ug[i] = d_rp_ug[i];
    if (i <= NU) d_cur_gu[i] = d_rp_gu[i];
}

__global__ void k_scatter(const int* __restrict__ sug, const int* __restrict__ dug,
                          const float* __restrict__ wug,
                          const int* __restrict__ sgu, const int* __restrict__ dgu,
                          const float* __restrict__ wgu) {
    int e = blockIdx.x * blockDim.x + threadIdx.x;
    if (e < NE) {
        int p = atomicAdd(&d_cur_ug[dug[e]], 1);
        d_es_ug[p] = sug[e];
        d_ws_ug[p] = wug[e];
        int q = atomicAdd(&d_cur_gu[dgu[e]], 1);
        d_es_gu[q] = sgu[e];
        d_ws_gu[q] = wgu[e];
    }
}

// ----------------------------------------------------------------------------
// Segment sum by CSR rows: out[row,:] = sum_j w_j * X[src_j,:]
// Block = 128 threads, one row per block, D/128 columns per thread.
// ----------------------------------------------------------------------------
template <int D>
__global__ void k_segsum(const float* __restrict__ X,
                         const int* __restrict__ rp,
                         const int* __restrict__ es,
                         const float* __restrict__ wv,
                         float* __restrict__ out) {
    constexpr int T = 128;
    constexpr int V = D / T;
    int row = blockIdx.x;
    int beg = rp[row], end = rp[row + 1];
    int tid = threadIdx.x;

    float acc[V];
#pragma unroll
    for (int v = 0; v < V; v++) acc[v] = 0.f;

    __shared__ int   ss[T];
    __shared__ float sw[T];

    for (int base = beg; base < end; base += T) {
        int cnt = min(T, end - base);
        if (tid < cnt) { ss[tid] = es[base + tid]; sw[tid] = wv[base + tid]; }
        __syncthreads();
        for (int j = 0; j < cnt; j++) {
            const float* xr = X + (size_t)ss[j] * D;
            float wj = sw[j];
#pragma unroll
            for (int v = 0; v < V; v++) acc[v] += wj * xr[tid + v * T];
        }
        __syncthreads();
    }
#pragma unroll
    for (int v = 0; v < V; v++) out[(size_t)row * D + tid + v * T] = acc[v];
}

// ----------------------------------------------------------------------------
// Fused SGEMM: C[M,256] = relu?( A1@W1 + (A2@W2)? + pre? + bias? )
// 128x128x8 tile, 256 threads, 8x8 per-thread microtile. N fixed at 256,
// grid.y = 2 (two 128-col halves). K1/K2 must be multiples of 8.
// ----------------------------------------------------------------------------
__global__ __launch_bounds__(256)
void k_gemm(const float* __restrict__ A1, const float* __restrict__ W1, int K1,
            const float* __restrict__ A2, const float* __restrict__ W2, int K2,
            const float* __restrict__ pre, const float* __restrict__ bias,
            float* __restrict__ C, int M, int relu) {
    constexpr int BM = 128, BN = 128, BK = 8;
    __shared__ float As[BK][BM + 4];
    __shared__ float Bs[BK][BN];

    int tid = threadIdx.x;
    int tx = tid & 15;        // 0..15  (cols)
    int ty = tid >> 4;        // 0..15  (rows)
    int brow = blockIdx.x * BM;
    int bcol = blockIdx.y * BN;

    float acc[8][8];
#pragma unroll
    for (int i = 0; i < 8; i++)
#pragma unroll
        for (int j = 0; j < 8; j++) acc[i][j] = 0.f;

    // A tile loader mapping
    int arow  = tid >> 1;          // 0..127
    int acol4 = (tid & 1) * 4;     // 0 or 4
    int grow  = brow + arow;
    bool aval = (grow < M);
    int crow  = aval ? grow : (M - 1);
    // W tile loader mapping
    int wrow  = tid >> 5;          // 0..7
    int wcol4 = (tid & 31) * 4;    // 0..124

    for (int pass = 0; pass < 2; pass++) {
        const float* A = pass ? A2 : A1;
        const float* W = pass ? W2 : W1;
        int K = pass ? K2 : K1;
        if (A == nullptr) continue;
        const float* Aptr = A + (size_t)crow * K;

        for (int k0 = 0; k0 < K; k0 += BK) {
            float4 av = aval ? *(const float4*)(Aptr + k0 + acol4)
                             : make_float4(0.f, 0.f, 0.f, 0.f);
            float4 wv = *(const float4*)(W + (size_t)(k0 + wrow) * 256 + bcol + wcol4);
            __syncthreads();
            As[acol4 + 0][arow] = av.x;
            As[acol4 + 1][arow] = av.y;
            As[acol4 + 2][arow] = av.z;
            As[acol4 + 3][arow] = av.w;
            *(float4*)&Bs[wrow][wcol4] = wv;
            __syncthreads();
#pragma unroll
            for (int k = 0; k < BK; k++) {
                float ra[8], rb[8];
#pragma unroll
                for (int i = 0; i < 8; i++) ra[i] = As[k][ty * 8 + i];
#pragma unroll
                for (int j = 0; j < 8; j++) rb[j] = Bs[k][tx * 8 + j];
#pragma unroll
                for (int i = 0; i < 8; i++)
#pragma unroll
                    for (int j = 0; j < 8; j++) acc[i][j] += ra[i] * rb[j];
            }
        }
        __syncthreads();
    }

    // Epilogue
    float bb[8];
#pragma unroll
    for (int j = 0; j < 8; j++) bb[j] = bias ? bias[bcol + tx * 8 + j] : 0.f;

#pragma unroll
    for (int i = 0; i < 8; i++) {
        int r = brow + ty * 8 + i;
        if (r >= M) continue;
        size_t off = (size_t)r * 256 + bcol + tx * 8;
#pragma unroll
        for (int j = 0; j < 8; j++) {
            float v = acc[i][j] + bb[j];
            if (pre) v += pre[off + j];
            if (relu) v = fmaxf(v, 0.f);
            C[off + j] = v;
        }
    }
}

// ----------------------------------------------------------------------------
// Decoder: out[s] = dot(u[row[s]], g[col[s]]) over 256 dims. One warp per s.
// ----------------------------------------------------------------------------
__global__ void k_decode(const float* __restrict__ u, const float* __restrict__ g,
                         const int* __restrict__ rows, const int* __restrict__ cols,
                         float* __restrict__ out) {
    int w = (blockIdx.x * blockDim.x + threadIdx.x) >> 5;
    int lane = threadIdx.x & 31;
    if (w >= NS) return;
    const float4* ur = (const float4*)(u + (size_t)rows[w] * 256);
    const float4* gr = (const float4*)(g + (size_t)cols[w] * 256);
    float acc = 0.f;
#pragma unroll
    for (int i = 0; i < 2; i++) {
        float4 a = ur[lane + i * 32];
        float4 b = gr[lane + i * 32];
        acc += a.x * b.x + a.y * b.y + a.z * b.z + a.w * b.w;
    }
#pragma unroll
    for (int o = 16; o; o >>= 1) acc += __shfl_down_sync(0xffffffffu, acc, o);
    if (lane == 0) out[w] = acc;
}

// ----------------------------------------------------------------------------
// Host side
// ----------------------------------------------------------------------------
static void run_layer(const float* u_prev, int du, const float* g_prev, int dg,
                      const float* Wr_ug, const float* b_ug, const float* Wo_g,
                      const float* Wr_gu, const float* b_gu, const float* Wo_u,
                      float* g_out, float* u_out, int relu,
                      float* p_msg_g, float* p_y, float* p_msg_u,
                      int* p_rp_ug, int* p_es_ug, float* p_ws_ug,
                      int* p_rp_gu, int* p_es_gu, float* p_ws_gu) {
    // users -> games (direct form): msg_g[NG,du] = segsum_ug(u_prev)
    if (du == 128)
        k_segsum<128><<<NG, 128>>>(u_prev, p_rp_ug, p_es_ug, p_ws_ug, p_msg_g);
    else
        k_segsum<256><<<NG, 128>>>(u_prev, p_rp_ug, p_es_ug, p_ws_ug, p_msg_g);
    // g_out = relu?(msg_g@Wr_ug + g_prev@Wo_g + b_ug)
    k_gemm<<<dim3((NG + 127) / 128, 2), 256>>>(p_msg_g, Wr_ug, du,
                                               g_prev, Wo_g, dg,
                                               nullptr, b_ug, g_out, NG, relu);
    // games -> users (commuted form): y = g_prev@Wr_gu  [NG,256]
    k_gemm<<<dim3((NG + 127) / 128, 2), 256>>>(g_prev, Wr_gu, dg,
                                               nullptr, nullptr, 0,
                                               nullptr, nullptr, p_y, NG, 0);
    // msg_u[NU,256] = segsum_gu(y)
    k_segsum<256><<<NU, 128>>>(p_y, p_rp_gu, p_es_gu, p_ws_gu, p_msg_u);
    // u_out = relu?(msg_u + u_prev@Wo_u + b_gu)
    k_gemm<<<dim3((NU + 127) / 128, 2), 256>>>(u_prev, Wo_u, du,
                                               nullptr, nullptr, 0,
                                               p_msg_u, b_gu, u_out, NU, relu);
}

extern "C" void kernel_launch(void* const* d_in, const int* in_sizes, int n_in,
                              void* d_out, int out_size) {
    // ---- input mapping (handles both metadata orderings) ----
    const float *x_user, *x_game, *emb_game, *ew_ug, *ew_gu;
    const int *src_ug, *dst_ug, *src_gu, *dst_gu, *srow, *scol;
    const float *Wrug[3], *bug[3], *Wog[3], *Wrgu[3], *bgu[3], *Wou[3];

    x_user   = (const float*)d_in[0];
    x_game   = (const float*)d_in[1];
    emb_game = (const float*)d_in[2];
    ew_ug    = (const float*)d_in[3];
    ew_gu    = (const float*)d_in[4];

    if (in_sizes[5] == NE) {
        // setup_inputs dict order
        src_ug = (const int*)d_in[5];
        dst_ug = (const int*)d_in[6];
        src_gu = (const int*)d_in[7];
        dst_gu = (const int*)d_in[8];
        srow   = (const int*)d_in[9];
        scol   = (const int*)d_in[10];
        for (int l = 0; l < 3; l++) {
            int b = 11 + 6 * l;
            Wrug[l] = (const float*)d_in[b + 0];
            bug[l]  = (const float*)d_in[b + 1];
            Wog[l]  = (const float*)d_in[b + 2];
            Wrgu[l] = (const float*)d_in[b + 3];
            bgu[l]  = (const float*)d_in[b + 4];
            Wou[l]  = (const float*)d_in[b + 5];
        }
    } else {
        // reference signature order
        for (int l = 0; l < 3; l++) {
            int b = 5 + 6 * l;
            Wrug[l] = (const float*)d_in[b + 0];
            bug[l]  = (const float*)d_in[b + 1];
            Wog[l]  = (const float*)d_in[b + 2];
            Wrgu[l] = (const float*)d_in[b + 3];
            bgu[l]  = (const float*)d_in[b + 4];
            Wou[l]  = (const float*)d_in[b + 5];
        }
        src_ug = (const int*)d_in[23];
        dst_ug = (const int*)d_in[24];
        src_gu = (const int*)d_in[25];
        dst_gu = (const int*)d_in[26];
        srow   = (const int*)d_in[27];
        scol   = (const int*)d_in[28];
    }

    // ---- scratch symbol addresses ----
    float *p_xg, *p_u0, *p_u1, *p_g0, *p_g1, *p_msg_g, *p_y, *p_msg_u;
    float *p_ws_ug, *p_ws_gu;
    int *p_rp_ug, *p_rp_gu, *p_es_ug, *p_es_gu;
    cudaGetSymbolAddress((void**)&p_xg, d_xg);
    cudaGetSymbolAddress((void**)&p_u0, d_u0);
    cudaGetSymbolAddress((void**)&p_u1, d_u1);
    cudaGetSymbolAddress((void**)&p_g0, d_g0);
    cudaGetSymbolAddress((void**)&p_g1, d_g1);
    cudaGetSymbolAddress((void**)&p_msg_g, d_msg_g);
    cudaGetSymbolAddress((void**)&p_y, d_y);
    cudaGetSymbolAddress((void**)&p_msg_u, d_msg_u);
    cudaGetSymbolAddress((void**)&p_rp_ug, d_rp_ug);
    cudaGetSymbolAddress((void**)&p_rp_gu, d_rp_gu);
    cudaGetSymbolAddress((void**)&p_es_ug, d_es_ug);
    cudaGetSymbolAddress((void**)&p_es_gu, d_es_gu);
    cudaGetSymbolAddress((void**)&p_ws_ug, d_ws_ug);
    cudaGetSymbolAddress((void**)&p_ws_gu, d_ws_gu);

    float* out = (float*)d_out;

    // ---- setup: concat game features, build CSR (both directions) ----
    k_concat<<<(NG * 64 + 255) / 256, 256>>>(x_game, emb_game);
    k_zero_counts<<<(NU + 256) / 256, 256>>>();
    k_hist<<<(NE + 255) / 256, 256>>>(dst_ug, dst_gu);
    k_scan<<<2, 1024>>>();
    k_cursor<<<(NU + 256) / 256, 256>>>();
    k_scatter<<<(NE + 255) / 256, 256>>>(src_ug, dst_ug, ew_ug,
                                         src_gu, dst_gu, ew_gu);

    // ---- 3 GraphConv layers ----
    // L1: inputs x_user[NU,128], xg[NG,128] -> g0, u0 (relu)
    run_layer(x_user, 128, p_xg, 128,
              Wrug[0], bug[0], Wog[0], Wrgu[0], bgu[0], Wou[0],
              p_g0, p_u0, 1,
              p_msg_g, p_y, p_msg_u,
              p_rp_ug, p_es_ug, p_ws_ug, p_rp_gu, p_es_gu, p_ws_gu);
    // L2: (u0, g0) -> g1, u1 (relu)
    run_layer(p_u0, 256, p_g0, 256,
              Wrug[1], bug[1], Wog[1], Wrgu[1], bgu[1], Wou[1],
              p_g1, p_u1, 1,
              p_msg_g, p_y, p_msg_u,
              p_rp_ug, p_es_ug, p_ws_ug, p_rp_gu, p_es_gu, p_ws_gu);
    // L3: (u1, g1) -> g0, u0 (no relu)
    run_layer(p_u1, 256, p_g1, 256,
              Wrug[2], bug[2], Wog[2], Wrgu[2], bgu[2], Wou[2],
              p_g0, p_u0, 0,
              p_msg_g, p_y, p_msg_u,
              p_rp_ug, p_es_ug, p_ws_ug, p_rp_gu, p_es_gu, p_ws_gu);

    // ---- decoder ----
    k_decode<<<(NS * 32 + 255) / 256, 256>>>(p_u0, p_g0, srow, scol, out);
    (void)n_in; (void)out_size;
}

// round 2
// speedup vs baseline: 1.0073x; 1.0073x over previous
#include <cuda_runtime.h>
#include <cstdint>

#define NU 100000
#define NG 20000
#define NE 1000000
#define NS 500000
#define HH 256

// ----------------------------------------------------------------------------
// Static device scratch (no runtime allocation allowed)
// ----------------------------------------------------------------------------
__device__ float d_xg[NG * 128];          // concat(x_game, emb_game)
__device__ float d_u0[(size_t)NU * HH];
__device__ float d_u1[(size_t)NU * HH];
__device__ float d_g0[NG * HH];
__device__ float d_g1[NG * HH];
__device__ float d_msg_g[NG * HH];
__device__ float d_y[NG * HH];
__device__ float d_msg_u[(size_t)NU * HH];

__device__ int   d_rp_ug[NG + 1];
__device__ int   d_rp_gu[NU + 1];
__device__ int   d_cur_ug[NG + 1];
__device__ int   d_cur_gu[NU + 1];
__device__ int   d_es_ug[NE];
__device__ float d_ws_ug[NE];
__device__ int   d_es_gu[NE];
__device__ float d_ws_gu[NE];

// ----------------------------------------------------------------------------
// Setup kernels
// ----------------------------------------------------------------------------
__global__ void k_concat(const float* __restrict__ xg64, const float* __restrict__ emb) {
    int i = blockIdx.x * blockDim.x + threadIdx.x;   // over NG*64
    if (i < NG * 64) {
        int r = i >> 6, c = i & 63;
        d_xg[r * 128 + c]      = xg64[i];
        d_xg[r * 128 + 64 + c] = emb[i];
    }
}

__global__ void k_zero_counts() {
    int i = blockIdx.x * blockDim.x + threadIdx.x;
    if (i <= NG) d_cur_ug[i] = 0;
    if (i <= NU) d_cur_gu[i] = 0;
}

__global__ void k_hist(const int* __restrict__ dug, const int* __restrict__ dgu) {
    int e = blockIdx.x * blockDim.x + threadIdx.x;
    if (e < NE) {
        atomicAdd(&d_cur_ug[dug[e]], 1);
        atomicAdd(&d_cur_gu[dgu[e]], 1);
    }
}

// Exclusive scan: block 0 scans games counts, block 1 scans users counts.
__global__ void k_scan() {
    int n; int* cnt; int* rp;
    if (blockIdx.x == 0) { n = NG; cnt = d_cur_ug; rp = d_rp_ug; }
    else                 { n = NU; cnt = d_cur_gu; rp = d_rp_gu; }
    __shared__ int s[1024];
    int tid = threadIdx.x;
    int carry = 0;
    for (int base = 0; base < n; base += 1024) {
        int x = (base + tid < n) ? cnt[base + tid] : 0;
        s[tid] = x;
        __syncthreads();
        for (int off = 1; off < 1024; off <<= 1) {
            int v = (tid >= off) ? s[tid - off] : 0;
            __syncthreads();
            s[tid] += v;
            __syncthreads();
        }
        if (base + tid < n) rp[base + tid] = carry + s[tid] - x;
        int tot = s[1023];
        __syncthreads();
        carry += tot;
    }
    if (tid == 0) rp[n] = carry;
}

__global__ void k_cursor() {
    int i = blockIdx.x * blockDim.x + threadIdx.x;
    if (i <= NG) d_cur_ug[i] = d_rp_ug[i];
    if (i <= NU) d_cur_gu[i] = d_rp_gu[i];
}

__global__ void k_scatter(const int* __restrict__ sug, const int* __restrict__ dug,
                          const float* __restrict__ wug,
                          const int* __restrict__ sgu, const int* __restrict__ dgu,
                          const float* __restrict__ wgu) {
    int e = blockIdx.x * blockDim.x + threadIdx.x;
    if (e < NE) {
        int p = atomicAdd(&d_cur_ug[dug[e]], 1);
        d_es_ug[p] = sug[e];
        d_ws_ug[p] = wug[e];
        int q = atomicAdd(&d_cur_gu[dgu[e]], 1);
        d_es_gu[q] = sgu[e];
        d_ws_gu[q] = wgu[e];
    }
}

// ----------------------------------------------------------------------------
// Segment sum by CSR rows: out[row,:] = sum_j w_j * X[src_j,:]
// Block = 128 threads, one row per block, D/128 columns per thread.
// ----------------------------------------------------------------------------
template <int D>
__global__ void k_segsum(const float* __restrict__ X,
                         const int* __restrict__ rp,
                         const int* __restrict__ es,
                         const float* __restrict__ wv,
                         float* __restrict__ out) {
    constexpr int T = 128;
    constexpr int V = D / T;
    int row = blockIdx.x;
    int beg = rp[row], end = rp[row + 1];
    int tid = threadIdx.x;

    float acc[V];
#pragma unroll
    for (int v = 0; v < V; v++) acc[v] = 0.f;

    __shared__ int   ss[T];
    __shared__ float sw[T];

    for (int base = beg; base < end; base += T) {
        int cnt = min(T, end - base);
        if (tid < cnt) { ss[tid] = es[base + tid]; sw[tid] = wv[base + tid]; }
        __syncthreads();
        for (int j = 0; j < cnt; j++) {
            const float* xr = X + (size_t)ss[j] * D;
            float wj = sw[j];
#pragma unroll
            for (int v = 0; v < V; v++) acc[v] += wj * xr[tid + v * T];
        }
        __syncthreads();
    }
#pragma unroll
    for (int v = 0; v < V; v++) out[(size_t)row * D + tid + v * T] = acc[v];
}

// ----------------------------------------------------------------------------
// Fused SGEMM: C[M,256] = relu?( A1@W1 + (A2@W2)? + pre? + bias? )
// 128x128x8 tile, 256 threads, 8x8 per-thread microtile. N fixed at 256,
// grid.y = 2 (two 128-col halves). K1/K2 must be multiples of 8.
// ----------------------------------------------------------------------------
__global__ __launch_bounds__(256)
void k_gemm(const float* __restrict__ A1, const float* __restrict__ W1, int K1,
            const float* __restrict__ A2, const float* __restrict__ W2, int K2,
            const float* __restrict__ pre, const float* __restrict__ bias,
            float* __restrict__ C, int M, int relu) {
    constexpr int BM = 128, BN = 128, BK = 8;
    __shared__ float As[BK][BM + 4];
    __shared__ float Bs[BK][BN];

    int tid = threadIdx.x;
    int tx = tid & 15;        // 0..15  (cols)
    int ty = tid >> 4;        // 0..15  (rows)
    int brow = blockIdx.x * BM;
    int bcol = blockIdx.y * BN;

    float acc[8][8];
#pragma unroll
    for (int i = 0; i < 8; i++)
#pragma unroll
        for (int j = 0; j < 8; j++) acc[i][j] = 0.f;

    // A tile loader mapping
    int arow  = tid >> 1;          // 0..127
    int acol4 = (tid & 1) * 4;     // 0 or 4
    int grow  = brow + arow;
    bool aval = (grow < M);
    int crow  = aval ? grow : (M - 1);
    // W tile loader mapping
    int wrow  = tid >> 5;          // 0..7
    int wcol4 = (tid & 31) * 4;    // 0..124

    for (int pass = 0; pass < 2; pass++) {
        const float* A = pass ? A2 : A1;
        const float* W = pass ? W2 : W1;
        int K = pass ? K2 : K1;
        if (A == nullptr) continue;
        const float* Aptr = A + (size_t)crow * K;

        for (int k0 = 0; k0 < K; k0 += BK) {
            float4 av = aval ? *(const float4*)(Aptr + k0 + acol4)
                             : make_float4(0.f, 0.f, 0.f, 0.f);
            float4 wv = *(const float4*)(W + (size_t)(k0 + wrow) * 256 + bcol + wcol4);
            __syncthreads();
            As[acol4 + 0][arow] = av.x;
            As[acol4 + 1][arow] = av.y;
            As[acol4 + 2][arow] = av.z;
            As[acol4 + 3][arow] = av.w;
            *(float4*)&Bs[wrow][wcol4] = wv;
            __syncthreads();
#pragma unroll
            for (int k = 0; k < BK; k++) {
                float ra[8], rb[8];
#pragma unroll
                for (int i = 0; i < 8; i++) ra[i] = As[k][ty * 8 + i];
#pragma unroll
                for (int j = 0; j < 8; j++) rb[j] = Bs[k][tx * 8 + j];
#pragma unroll
                for (int i = 0; i < 8; i++)
#pragma unroll
                    for (int j = 0; j < 8; j++) acc[i][j] += ra[i] * rb[j];
            }
        }
        __syncthreads();
    }

    // Epilogue
    float bb[8];
#pragma unroll
    for (int j = 0; j < 8; j++) bb[j] = bias ? bias[bcol + tx * 8 + j] : 0.f;

#pragma unroll
    for (int i = 0; i < 8; i++) {
        int r = brow + ty * 8 + i;
        if (r >= M) continue;
        size_t off = (size_t)r * 256 + bcol + tx * 8;
#pragma unroll
        for (int j = 0; j < 8; j++) {
            float v = acc[i][j] + bb[j];
            if (pre) v += pre[off + j];
            if (relu) v = fmaxf(v, 0.f);
            C[off + j] = v;
        }
    }
}

// ----------------------------------------------------------------------------
// Decoder: out[s] = dot(u[row[s]], g[col[s]]) over 256 dims. One warp per s.
// ----------------------------------------------------------------------------
__global__ void k_decode(const float* __restrict__ u, const float* __restrict__ g,
                         const int* __restrict__ rows, const int* __restrict__ cols,
                         float* __restrict__ out) {
    int w = (blockIdx.x * blockDim.x + threadIdx.x) >> 5;
    int lane = threadIdx.x & 31;
    if (w >= NS) return;
    const float4* ur = (const float4*)(u + (size_t)rows[w] * 256);
    const float4* gr = (const float4*)(g + (size_t)cols[w] * 256);
    float acc = 0.f;
#pragma unroll
    for (int i = 0; i < 2; i++) {
        float4 a = ur[lane + i * 32];
        float4 b = gr[lane + i * 32];
        acc += a.x * b.x + a.y * b.y + a.z * b.z + a.w * b.w;
    }
#pragma unroll
    for (int o = 16; o; o >>= 1) acc += __shfl_down_sync(0xffffffffu, acc, o);
    if (lane == 0) out[w] = acc;
}

// ----------------------------------------------------------------------------
// Host side
// ----------------------------------------------------------------------------
static void run_layer(const float* u_prev, int du, const float* g_prev, int dg,
                      const float* Wr_ug, const float* b_ug, const float* Wo_g,
                      const float* Wr_gu, const float* b_gu, const float* Wo_u,
                      float* g_out, float* u_out, int relu,
                      float* p_msg_g, float* p_y, float* p_msg_u,
                      int* p_rp_ug, int* p_es_ug, float* p_ws_ug,
                      int* p_rp_gu, int* p_es_gu, float* p_ws_gu) {
    // users -> games (direct form): msg_g[NG,du] = segsum_ug(u_prev)
    if (du == 128)
        k_segsum<128><<<NG, 128>>>(u_prev, p_rp_ug, p_es_ug, p_ws_ug, p_msg_g);
    else
        k_segsum<256><<<NG, 128>>>(u_prev, p_rp_ug, p_es_ug, p_ws_ug, p_msg_g);
    // g_out = relu?(msg_g@Wr_ug + g_prev@Wo_g + b_ug)
    k_gemm<<<dim3((NG + 127) / 128, 2), 256>>>(p_msg_g, Wr_ug, du,
                                               g_prev, Wo_g, dg,
                                               nullptr, b_ug, g_out, NG, relu);
    // games -> users (commuted form): y = g_prev@Wr_gu  [NG,256]
    k_gemm<<<dim3((NG + 127) / 128, 2), 256>>>(g_prev, Wr_gu, dg,
                                               nullptr, nullptr, 0,
                                               nullptr, nullptr, p_y, NG, 0);
    // msg_u[NU,256] = segsum_gu(y)
    k_segsum<256><<<NU, 128>>>(p_y, p_rp_gu, p_es_gu, p_ws_gu, p_msg_u);
    // u_out = relu?(msg_u + u_prev@Wo_u + b_gu)
    k_gemm<<<dim3((NU + 127) / 128, 2), 256>>>(u_prev, Wo_u, du,
                                               nullptr, nullptr, 0,
                                               p_msg_u, b_gu, u_out, NU, relu);
}

extern "C" void kernel_launch(void* const* d_in, const int* in_sizes, int n_in,
                              void* d_out, int out_size) {
    // ---- input mapping (handles both metadata orderings) ----
    const float *x_user, *x_game, *emb_game, *ew_ug, *ew_gu;
    const int *src_ug, *dst_ug, *src_gu, *dst_gu, *srow, *scol;
    const float *Wrug[3], *bug[3], *Wog[3], *Wrgu[3], *bgu[3], *Wou[3];

    x_user   = (const float*)d_in[0];
    x_game   = (const float*)d_in[1];
    emb_game = (const float*)d_in[2];
    ew_ug    = (const float*)d_in[3];
    ew_gu    = (const float*)d_in[4];

    if (in_sizes[5] == NE) {
        // setup_inputs dict order
        src_ug = (const int*)d_in[5];
        dst_ug = (const int*)d_in[6];
        src_gu = (const int*)d_in[7];
        dst_gu = (const int*)d_in[8];
        srow   = (const int*)d_in[9];
        scol   = (const int*)d_in[10];
        for (int l = 0; l < 3; l++) {
            int b = 11 + 6 * l;
            Wrug[l] = (const float*)d_in[b + 0];
            bug[l]  = (const float*)d_in[b + 1];
            Wog[l]  = (const float*)d_in[b + 2];
            Wrgu[l] = (const float*)d_in[b + 3];
            bgu[l]  = (const float*)d_in[b + 4];
            Wou[l]  = (const float*)d_in[b + 5];
        }
    } else {
        // reference signature order
        for (int l = 0; l < 3; l++) {
            int b = 5 + 6 * l;
            Wrug[l] = (const float*)d_in[b + 0];
            bug[l]  = (const float*)d_in[b + 1];
            Wog[l]  = (const float*)d_in[b + 2];
            Wrgu[l] = (const float*)d_in[b + 3];
            bgu[l]  = (const float*)d_in[b + 4];
            Wou[l]  = (const float*)d_in[b + 5];
        }
        src_ug = (const int*)d_in[23];
        dst_ug = (const int*)d_in[24];
        src_gu = (const int*)d_in[25];
        dst_gu = (const int*)d_in[26];
        srow   = (const int*)d_in[27];
        scol   = (const int*)d_in[28];
    }

    // ---- scratch symbol addresses ----
    float *p_xg, *p_u0, *p_u1, *p_g0, *p_g1, *p_msg_g, *p_y, *p_msg_u;
    float *p_ws_ug, *p_ws_gu;
    int *p_rp_ug, *p_rp_gu, *p_es_ug, *p_es_gu;
    cudaGetSymbolAddress((void**)&p_xg, d_xg);
    cudaGetSymbolAddress((void**)&p_u0, d_u0);
    cudaGetSymbolAddress((void**)&p_u1, d_u1);
    cudaGetSymbolAddress((void**)&p_g0, d_g0);
    cudaGetSymbolAddress((void**)&p_g1, d_g1);
    cudaGetSymbolAddress((void**)&p_msg_g, d_msg_g);
    cudaGetSymbolAddress((void**)&p_y, d_y);
    cudaGetSymbolAddress((void**)&p_msg_u, d_msg_u);
    cudaGetSymbolAddress((void**)&p_rp_ug, d_rp_ug);
    cudaGetSymbolAddress((void**)&p_rp_gu, d_rp_gu);
    cudaGetSymbolAddress((void**)&p_es_ug, d_es_ug);
    cudaGetSymbolAddress((void**)&p_es_gu, d_es_gu);
    cudaGetSymbolAddress((void**)&p_ws_ug, d_ws_ug);
    cudaGetSymbolAddress((void**)&p_ws_gu, d_ws_gu);

    float* out = (float*)d_out;

    // ---- setup: concat game features, build CSR (both directions) ----
    k_concat<<<(NG * 64 + 255) / 256, 256>>>(x_game, emb_game);
    k_zero_counts<<<(NU + 256) / 256, 256>>>();
    k_hist<<<(NE + 255) / 256, 256>>>(dst_ug, dst_gu);
    k_scan<<<2, 1024>>>();
    k_cursor<<<(NU + 256) / 256, 256>>>();
    k_scatter<<<(NE + 255) / 256, 256>>>(src_ug, dst_ug, ew_ug,
                                         src_gu, dst_gu, ew_gu);

    // ---- 3 GraphConv layers ----
    // L1: inputs x_user[NU,128], xg[NG,128] -> g0, u0 (relu)
    run_layer(x_user, 128, p_xg, 128,
              Wrug[0], bug[0], Wog[0], Wrgu[0], bgu[0], Wou[0],
              p_g0, p_u0, 1,
              p_msg_g, p_y, p_msg_u,
              p_rp_ug, p_es_ug, p_ws_ug, p_rp_gu, p_es_gu, p_ws_gu);
    // L2: (u0, g0) -> g1, u1 (relu)
    run_layer(p_u0, 256, p_g0, 256,
              Wrug[1], bug[1], Wog[1], Wrgu[1], bgu[1], Wou[1],
              p_g1, p_u1, 1,
              p_msg_g, p_y, p_msg_u,
              p_rp_ug, p_es_ug, p_ws_ug, p_rp_gu, p_es_gu, p_ws_gu);
    // L3: (u1, g1) -> g0, u0 (no relu)
    run_layer(p_u1, 256, p_g1, 256,
              Wrug[2], bug[2], Wog[2], Wrgu[2], bgu[2], Wou[2],
              p_g0, p_u0, 0,
              p_msg_g, p_y, p_msg_u,
              p_rp_ug, p_es_ug, p_ws_ug, p_rp_gu, p_es_gu, p_ws_gu);

    // ---- decoder ----
    k_decode<<<(NS * 32 + 255) / 256, 256>>>(p_u0, p_g0, srow, scol, out);
    (void)n_in; (void)out_size;
}

// round 5
// speedup vs baseline: 1.0793x; 1.0715x over previous
#include <cuda_runtime.h>
#include <cstdint>

#define NU 100000
#define NG 20000
#define NE 1000000
#define NS 500000
#define HH 256

// ----------------------------------------------------------------------------
// Static device scratch (no runtime allocation allowed)
// ----------------------------------------------------------------------------
__device__ float d_xg[NG * 128];          // concat(x_game, emb_game)
__device__ float d_u0[(size_t)NU * HH];
__device__ float d_u1[(size_t)NU * HH];
__device__ float d_g0[NG * HH];
__device__ float d_g1[NG * HH];
__device__ float d_msg_g[NG * HH];
__device__ float d_y[NG * HH];
__device__ float d_msg_u[(size_t)NU * HH];

__device__ int   d_rp_ug[NG + 1];
__device__ int   d_rp_gu[NU + 1];
__device__ int   d_cur_ug[NG + 1];
__device__ int   d_cur_gu[NU + 1];
__device__ int   d_es_ug[NE];
__device__ float d_ws_ug[NE];
__device__ int   d_es_gu[NE];
__device__ float d_ws_gu[NE];

// ----------------------------------------------------------------------------
// Setup kernels
// ----------------------------------------------------------------------------
__global__ void k_concat(const float* __restrict__ xg64, const float* __restrict__ emb) {
    int i = blockIdx.x * blockDim.x + threadIdx.x;   // over NG*64
    if (i < NG * 64) {
        int r = i >> 6, c = i & 63;
        d_xg[r * 128 + c]      = xg64[i];
        d_xg[r * 128 + 64 + c] = emb[i];
    }
}

__global__ void k_zero_counts() {
    int i = blockIdx.x * blockDim.x + threadIdx.x;
    if (i <= NG) d_cur_ug[i] = 0;
    if (i <= NU) d_cur_gu[i] = 0;
}

__global__ void k_hist(const int* __restrict__ dug, const int* __restrict__ dgu) {
    int e = blockIdx.x * blockDim.x + threadIdx.x;
    if (e < NE) {
        atomicAdd(&d_cur_ug[dug[e]], 1);
        atomicAdd(&d_cur_gu[dgu[e]], 1);
    }
}

// Exclusive scan: block 0 scans games counts, block 1 scans users counts.
// Chunk-per-thread serial sum -> warp-shuffle block scan -> serial prefix write.
__global__ void k_scan() {
    int n; int* cnt; int* rp;
    if (blockIdx.x == 0) { n = NG; cnt = d_cur_ug; rp = d_rp_ug; }
    else                 { n = NU; cnt = d_cur_gu; rp = d_rp_gu; }
    const int T = 1024;
    int tid = threadIdx.x;
    int chunk = (n + T - 1) / T;
    int beg = tid * chunk;
    int end = min(beg + chunk, n);

    int s = 0;
    for (int i = beg; i < end; i++) s += cnt[i];

    // block-wide exclusive scan of s
    __shared__ int warpsum[32];
    int lane = tid & 31, wid = tid >> 5;
    int v = s;
#pragma unroll
    for (int o = 1; o < 32; o <<= 1) {
        int t = __shfl_up_sync(0xffffffffu, v, o);
        if (lane >= o) v += t;
    }
    if (lane == 31) warpsum[wid] = v;
    __syncthreads();
    if (wid == 0) {
        int w = warpsum[lane];
#pragma unroll
        for (int o = 1; o < 32; o <<= 1) {
            int t = __shfl_up_sync(0xffffffffu, w, o);
            if (lane >= o) w += t;
        }
        warpsum[lane] = w;
    }
    __syncthreads();
    int run = v - s + (wid > 0 ? warpsum[wid - 1] : 0);   // exclusive prefix

    for (int i = beg; i < end; i++) {
        rp[i] = run;
        run += cnt[i];
    }
    if (beg < n && end == n) rp[n] = run;
}

__global__ void k_cursor() {
    int i = blockIdx.x * blockDim.x + threadIdx.x;
    if (i <= NG) d_cur_ug[i] = d_rp_ug[i];
    if (i <= NU) d_cur_gu[i] = d_rp_gu[i];
}

__global__ void k_scatter(const int* __restrict__ sug, const int* __restrict__ dug,
                          const float* __restrict__ wug,
                          const int* __restrict__ sgu, const int* __restrict__ dgu,
                          const float* __restrict__ wgu) {
    int e = blockIdx.x * blockDim.x + threadIdx.x;
    if (e < NE) {
        int p = atomicAdd(&d_cur_ug[dug[e]], 1);
        d_es_ug[p] = sug[e];
        d_ws_ug[p] = wug[e];
        int q = atomicAdd(&d_cur_gu[dgu[e]], 1);
        d_es_gu[q] = sgu[e];
        d_ws_gu[q] = wgu[e];
    }
}

// ----------------------------------------------------------------------------
// Segment sum by CSR rows: out[row,:] = sum_j w_j * X[src_j,:]
// Block = 128 threads, one row per block. D=256 uses float2 lanes.
// ----------------------------------------------------------------------------
__global__ void k_segsum256(const float* __restrict__ X,
                            const int* __restrict__ rp,
                            const int* __restrict__ es,
                            const float* __restrict__ wv,
                            float* __restrict__ out) {
    constexpr int T = 128;
    int row = blockIdx.x;
    int beg = rp[row], end = rp[row + 1];
    int tid = threadIdx.x;

    float2 acc = make_float2(0.f, 0.f);
    __shared__ int   ss[T];
    __shared__ float sw[T];

    for (int base = beg; base < end; base += T) {
        int cnt = min(T, end - base);
        if (tid < cnt) { ss[tid] = es[base + tid]; sw[tid] = wv[base + tid]; }
        __syncthreads();
#pragma unroll 4
        for (int j = 0; j < cnt; j++) {
            const float2* xr = (const float2*)(X + (size_t)ss[j] * 256);
            float wj = sw[j];
            float2 x = xr[tid];
            acc.x += wj * x.x;
            acc.y += wj * x.y;
        }
        __syncthreads();
    }
    ((float2*)(out + (size_t)row * 256))[tid] = acc;
}

__global__ void k_segsum128(const float* __restrict__ X,
                            const int* __restrict__ rp,
                            const int* __restrict__ es,
                            const float* __restrict__ wv,
                            float* __restrict__ out) {
    constexpr int T = 128;
    int row = blockIdx.x;
    int beg = rp[row], end = rp[row + 1];
    int tid = threadIdx.x;

    float acc = 0.f;
    __shared__ int   ss[T];
    __shared__ float sw[T];

    for (int base = beg; base < end; base += T) {
        int cnt = min(T, end - base);
        if (tid < cnt) { ss[tid] = es[base + tid]; sw[tid] = wv[base + tid]; }
        __syncthreads();
#pragma unroll 4
        for (int j = 0; j < cnt; j++) {
            acc += sw[j] * X[(size_t)ss[j] * 128 + tid];
        }
        __syncthreads();
    }
    out[(size_t)row * 128 + tid] = acc;
}

// ----------------------------------------------------------------------------
// Fused SGEMM: C[M,256] = relu?( A1@W1 + (A2@W2)? + pre? + bias? )
// 128x128x16 tile, double-buffered smem, 256 threads, 8x8 microtile.
// N fixed at 256, grid.y = 2. K1/K2 must be multiples of 16.
// ----------------------------------------------------------------------------
__global__ __launch_bounds__(256)
void k_gemm(const float* __restrict__ A1, const float* __restrict__ W1, int K1,
            const float* __restrict__ A2, const float* __restrict__ W2, int K2,
            const float* __restrict__ pre, const float* __restrict__ bias,
            float* __restrict__ C, int M, int relu) {
    constexpr int BM = 128, BN = 128, BK = 16;
    __shared__ float As[2][BK][BM + 4];
    __shared__ float Bs[2][BK][BN];

    int tid = threadIdx.x;
    int tx = tid & 15;        // 0..15  (cols)
    int ty = tid >> 4;        // 0..15  (rows)
    int brow = blockIdx.x * BM;
    int bcol = blockIdx.y * BN;

    float acc[8][8];
#pragma unroll
    for (int i = 0; i < 8; i++)
#pragma unroll
        for (int j = 0; j < 8; j++) acc[i][j] = 0.f;

    // A tile loader: 128x16 = 512 float4s; this thread loads rows ar, ar+64
    int ar  = tid >> 2;            // 0..63
    int ac4 = (tid & 3) * 4;       // 0,4,8,12
    int gr0 = brow + ar, gr1 = brow + ar + 64;
    bool av0 = (gr0 < M), av1 = (gr1 < M);
    int cr0 = av0 ? gr0 : (M - 1);
    int cr1 = av1 ? gr1 : (M - 1);
    // W tile loader: 16x128 = 512 float4s; rows wr, wr+8
    int wr  = tid >> 5;            // 0..7
    int wc4 = (tid & 31) * 4;      // 0..124

    const float4 f4z = make_float4(0.f, 0.f, 0.f, 0.f);

    for (int pass = 0; pass < 2; pass++) {
        const float* A = pass ? A2 : A1;
        const float* W = pass ? W2 : W1;
        int K = pass ? K2 : K1;
        if (A == nullptr) continue;
        const float* Ap0 = A + (size_t)cr0 * K;
        const float* Ap1 = A + (size_t)cr1 * K;

        // guard: previous pass's last compute must finish before reuse of buffers
        __syncthreads();

        // preload tile k0=0 into buffer 0
        {
            float4 a0 = av0 ? *(const float4*)(Ap0 + ac4) : f4z;
            float4 a1 = av1 ? *(const float4*)(Ap1 + ac4) : f4z;
            float4 w0 = *(const float4*)(W + (size_t)wr * 256 + bcol + wc4);
            float4 w1 = *(const float4*)(W + (size_t)(wr + 8) * 256 + bcol + wc4);
            As[0][ac4 + 0][ar] = a0.x; As[0][ac4 + 1][ar] = a0.y;
            As[0][ac4 + 2][ar] = a0.z; As[0][ac4 + 3][ar] = a0.w;
            As[0][ac4 + 0][ar + 64] = a1.x; As[0][ac4 + 1][ar + 64] = a1.y;
            As[0][ac4 + 2][ar + 64] = a1.z; As[0][ac4 + 3][ar + 64] = a1.w;
            *(float4*)&Bs[0][wr][wc4] = w0;
            *(float4*)&Bs[0][wr + 8][wc4] = w1;
        }
        __syncthreads();

        int buf = 0;
        for (int k0 = 0; k0 < K; k0 += BK) {
            bool more = (k0 + BK) < K;
            float4 na0, na1, nw0, nw1;
            if (more) {
                int kn = k0 + BK;
                na0 = av0 ? *(const float4*)(Ap0 + kn + ac4) : f4z;
                na1 = av1 ? *(const float4*)(Ap1 + kn + ac4) : f4z;
                nw0 = *(const float4*)(W + (size_t)(kn + wr) * 256 + bcol + wc4);
                nw1 = *(const float4*)(W + (size_t)(kn + wr + 8) * 256 + bcol + wc4);
            }
#pragma unroll
            for (int k = 0; k < BK; k++) {
                float ra[8], rb[8];
#pragma unroll
                for (int i = 0; i < 8; i++) ra[i] = As[buf][k][ty * 8 + i];
#pragma unroll
                for (int j = 0; j < 8; j++) rb[j] = Bs[buf][k][tx * 8 + j];
#pragma unroll
                for (int i = 0; i < 8; i++)
#pragma unroll
                    for (int j = 0; j < 8; j++) acc[i][j] += ra[i] * rb[j];
            }
            if (more) {
                int nb = buf ^ 1;
                As[nb][ac4 + 0][ar] = na0.x; As[nb][ac4 + 1][ar] = na0.y;
                As[nb][ac4 + 2][ar] = na0.z; As[nb][ac4 + 3][ar] = na0.w;
                As[nb][ac4 + 0][ar + 64] = na1.x; As[nb][ac4 + 1][ar + 64] = na1.y;
                As[nb][ac4 + 2][ar + 64] = na1.z; As[nb][ac4 + 3][ar + 64] = na1.w;
                *(float4*)&Bs[nb][wr][wc4] = nw0;
                *(float4*)&Bs[nb][wr + 8][wc4] = nw1;
                __syncthreads();
            }
            buf ^= 1;
        }
    }

    // Epilogue
    float bb[8];
#pragma unroll
    for (int j = 0; j < 8; j++) bb[j] = bias ? bias[bcol + tx * 8 + j] : 0.f;

#pragma unroll
    for (int i = 0; i < 8; i++) {
        int r = brow + ty * 8 + i;
        if (r >= M) continue;
        size_t off = (size_t)r * 256 + bcol + tx * 8;
#pragma unroll
        for (int j = 0; j < 8; j++) {
            float v = acc[i][j] + bb[j];
            if (pre) v += pre[off + j];
            if (relu) v = fmaxf(v, 0.f);
            C[off + j] = v;
        }
    }
}

// ----------------------------------------------------------------------------
// Decoder: out[s] = dot(u[row[s]], g[col[s]]) over 256 dims. One warp per s.
// ----------------------------------------------------------------------------
__global__ void k_decode(const float* __restrict__ u, const float* __restrict__ g,
                         const int* __restrict__ rows, const int* __restrict__ cols,
                         float* __restrict__ out) {
    int w = (blockIdx.x * blockDim.x + threadIdx.x) >> 5;
    int lane = threadIdx.x & 31;
    if (w >= NS) return;
    const float4* ur = (const float4*)(u + (size_t)rows[w] * 256);
    const float4* gr = (const float4*)(g + (size_t)cols[w] * 256);
    float acc = 0.f;
#pragma unroll
    for (int i = 0; i < 2; i++) {
        float4 a = ur[lane + i * 32];
        float4 b = gr[lane + i * 32];
        acc += a.x * b.x + a.y * b.y + a.z * b.z + a.w * b.w;
    }
#pragma unroll
    for (int o = 16; o; o >>= 1) acc += __shfl_down_sync(0xffffffffu, acc, o);
    if (lane == 0) out[w] = acc;
}

// ----------------------------------------------------------------------------
// Host side
// ----------------------------------------------------------------------------
static void run_layer(const float* u_prev, int du, const float* g_prev, int dg,
                      const float* Wr_ug, const float* b_ug, const float* Wo_g,
                      const float* Wr_gu, const float* b_gu, const float* Wo_u,
                      float* g_out, float* u_out, int relu,
                      float* p_msg_g, float* p_y, float* p_msg_u,
                      int* p_rp_ug, int* p_es_ug, float* p_ws_ug,
                      int* p_rp_gu, int* p_es_gu, float* p_ws_gu) {
    // users -> games (direct form): msg_g[NG,du] = segsum_ug(u_prev)
    if (du == 128)
        k_segsum128<<<NG, 128>>>(u_prev, p_rp_ug, p_es_ug, p_ws_ug, p_msg_g);
    else
        k_segsum256<<<NG, 128>>>(u_prev, p_rp_ug, p_es_ug, p_ws_ug, p_msg_g);
    // g_out = relu?(msg_g@Wr_ug + g_prev@Wo_g + b_ug)
    k_gemm<<<dim3((NG + 127) / 128, 2), 256>>>(p_msg_g, Wr_ug, du,
                                               g_prev, Wo_g, dg,
                                               nullptr, b_ug, g_out, NG, relu);
    // games -> users (commuted form): y = g_prev@Wr_gu  [NG,256]
    k_gemm<<<dim3((NG + 127) / 128, 2), 256>>>(g_prev, Wr_gu, dg,
                                               nullptr, nullptr, 0,
                                               nullptr, nullptr, p_y, NG, 0);
    // msg_u[NU,256] = segsum_gu(y)
    k_segsum256<<<NU, 128>>>(p_y, p_rp_gu, p_es_gu, p_ws_gu, p_msg_u);
    // u_out = relu?(msg_u + u_prev@Wo_u + b_gu)
    k_gemm<<<dim3((NU + 127) / 128, 2), 256>>>(u_prev, Wo_u, du,
                                               nullptr, nullptr, 0,
                                               p_msg_u, b_gu, u_out, NU, relu);
}

extern "C" void kernel_launch(void* const* d_in, const int* in_sizes, int n_in,
                              void* d_out, int out_size) {
    // ---- input mapping (handles both metadata orderings) ----
    const float *x_user, *x_game, *emb_game, *ew_ug, *ew_gu;
    const int *src_ug, *dst_ug, *src_gu, *dst_gu, *srow, *scol;
    const float *Wrug[3], *bug[3], *Wog[3], *Wrgu[3], *bgu[3], *Wou[3];

    x_user   = (const float*)d_in[0];
    x_game   = (const float*)d_in[1];
    emb_game = (const float*)d_in[2];
    ew_ug    = (const float*)d_in[3];
    ew_gu    = (const float*)d_in[4];

    if (in_sizes[5] == NE) {
        // setup_inputs dict order
        src_ug = (const int*)d_in[5];
        dst_ug = (const int*)d_in[6];
        src_gu = (const int*)d_in[7];
        dst_gu = (const int*)d_in[8];
        srow   = (const int*)d_in[9];
        scol   = (const int*)d_in[10];
        for (int l = 0; l < 3; l++) {
            int b = 11 + 6 * l;
            Wrug[l] = (const float*)d_in[b + 0];
            bug[l]  = (const float*)d_in[b + 1];
            Wog[l]  = (const float*)d_in[b + 2];
            Wrgu[l] = (const float*)d_in[b + 3];
            bgu[l]  = (const float*)d_in[b + 4];
            Wou[l]  = (const float*)d_in[b + 5];
        }
    } else {
        // reference signature order
        for (int l = 0; l < 3; l++) {
            int b = 5 + 6 * l;
            Wrug[l] = (const float*)d_in[b + 0];
            bug[l]  = (const float*)d_in[b + 1];
            Wog[l]  = (const float*)d_in[b + 2];
            Wrgu[l] = (const float*)d_in[b + 3];
            bgu[l]  = (const float*)d_in[b + 4];
            Wou[l]  = (const float*)d_in[b + 5];
        }
        src_ug = (const int*)d_in[23];
        dst_ug = (const int*)d_in[24];
        src_gu = (const int*)d_in[25];
        dst_gu = (const int*)d_in[26];
        srow   = (const int*)d_in[27];
        scol   = (const int*)d_in[28];
    }

    // ---- scratch symbol addresses ----
    float *p_xg, *p_u0, *p_u1, *p_g0, *p_g1, *p_msg_g, *p_y, *p_msg_u;
    float *p_ws_ug, *p_ws_gu;
    int *p_rp_ug, *p_rp_gu, *p_es_ug, *p_es_gu;
    cudaGetSymbolAddress((void**)&p_xg, d_xg);
    cudaGetSymbolAddress((void**)&p_u0, d_u0);
    cudaGetSymbolAddress((void**)&p_u1, d_u1);
    cudaGetSymbolAddress((void**)&p_g0, d_g0);
    cudaGetSymbolAddress((void**)&p_g1, d_g1);
    cudaGetSymbolAddress((void**)&p_msg_g, d_msg_g);
    cudaGetSymbolAddress((void**)&p_y, d_y);
    cudaGetSymbolAddress((void**)&p_msg_u, d_msg_u);
    cudaGetSymbolAddress((void**)&p_rp_ug, d_rp_ug);
    cudaGetSymbolAddress((void**)&p_rp_gu, d_rp_gu);
    cudaGetSymbolAddress((void**)&p_es_ug, d_es_ug);
    cudaGetSymbolAddress((void**)&p_es_gu, d_es_gu);
    cudaGetSymbolAddress((void**)&p_ws_ug, d_ws_ug);
    cudaGetSymbolAddress((void**)&p_ws_gu, d_ws_gu);

    float* out = (float*)d_out;

    // ---- setup: concat game features, build CSR (both directions) ----
    k_concat<<<(NG * 64 + 255) / 256, 256>>>(x_game, emb_game);
    k_zero_counts<<<(NU + 256) / 256, 256>>>();
    k_hist<<<(NE + 255) / 256, 256>>>(dst_ug, dst_gu);
    k_scan<<<2, 1024>>>();
    k_cursor<<<(NU + 256) / 256, 256>>>();
    k_scatter<<<(NE + 255) / 256, 256>>>(src_ug, dst_ug, ew_ug,
                                         src_gu, dst_gu, ew_gu);

    // ---- 3 GraphConv layers ----
    run_layer(x_user, 128, p_xg, 128,
              Wrug[0], bug[0], Wog[0], Wrgu[0], bgu[0], Wou[0],
              p_g0, p_u0, 1,
              p_msg_g, p_y, p_msg_u,
              p_rp_ug, p_es_ug, p_ws_ug, p_rp_gu, p_es_gu, p_ws_gu);
    run_layer(p_u0, 256, p_g0, 256,
              Wrug[1], bug[1], Wog[1], Wrgu[1], bgu[1], Wou[1],
              p_g1, p_u1, 1,
              p_msg_g, p_y, p_msg_u,
              p_rp_ug, p_es_ug, p_ws_ug, p_rp_gu, p_es_gu, p_ws_gu);
    run_layer(p_u1, 256, p_g1, 256,
              Wrug[2], bug[2], Wog[2], Wrgu[2], bgu[2], Wou[2],
              p_g0, p_u0, 0,
              p_msg_g, p_y, p_msg_u,
              p_rp_ug, p_es_ug, p_ws_ug, p_rp_gu, p_es_gu, p_ws_gu);

    // ---- decoder ----
    k_decode<<<(NS * 32 + 255) / 256, 256>>>(p_u0, p_g0, srow, scol, out);
    (void)n_in; (void)out_size;
}

// round 6
// speedup vs baseline: 1.0804x; 1.0010x over previous
#include <cuda_runtime.h>
#include <cstdint>

#define NU 100000
#define NG 20000
#define NE 1000000
#define NS 500000
#define HH 256

// ----------------------------------------------------------------------------
// Static device scratch (no runtime allocation allowed)
// ----------------------------------------------------------------------------
__device__ float d_xg[NG * 128];          // concat(x_game, emb_game)
__device__ float d_u0[(size_t)NU * HH];
__device__ float d_u1[(size_t)NU * HH];
__device__ float d_g0[NG * HH];
__device__ float d_g1[NG * HH];
__device__ float d_msg_g[NG * HH];
__device__ float d_y[NG * HH];
__device__ float d_msg_u[(size_t)NU * HH];

__device__ int   d_rp_ug[NG + 1];
__device__ int   d_rp_gu[NU + 1];
__device__ int   d_cur_ug[NG + 1];
__device__ int   d_cur_gu[NU + 1];
__device__ int   d_es_ug[NE];
__device__ float d_ws_ug[NE];
__device__ int   d_es_gu[NE];
__device__ float d_ws_gu[NE];

// ----------------------------------------------------------------------------
// Setup kernels
// ----------------------------------------------------------------------------
__global__ void k_concat(const float* __restrict__ xg64, const float* __restrict__ emb) {
    int i = blockIdx.x * blockDim.x + threadIdx.x;   // over NG*64
    if (i < NG * 64) {
        int r = i >> 6, c = i & 63;
        d_xg[r * 128 + c]      = xg64[i];
        d_xg[r * 128 + 64 + c] = emb[i];
    }
}

__global__ void k_zero_counts() {
    int i = blockIdx.x * blockDim.x + threadIdx.x;
    if (i <= NG) d_cur_ug[i] = 0;
    if (i <= NU) d_cur_gu[i] = 0;
}

__global__ void k_hist(const int* __restrict__ dug, const int* __restrict__ dgu) {
    int e = blockIdx.x * blockDim.x + threadIdx.x;
    if (e < NE) {
        atomicAdd(&d_cur_ug[dug[e]], 1);
        atomicAdd(&d_cur_gu[dgu[e]], 1);
    }
}

// Exclusive scan: block 0 scans games counts, block 1 scans users counts.
// Chunk-per-thread serial sum -> warp-shuffle block scan -> serial prefix write.
__global__ void k_scan() {
    int n; int* cnt; int* rp;
    if (blockIdx.x == 0) { n = NG; cnt = d_cur_ug; rp = d_rp_ug; }
    else                 { n = NU; cnt = d_cur_gu; rp = d_rp_gu; }
    const int T = 1024;
    int tid = threadIdx.x;
    int chunk = (n + T - 1) / T;
    int beg = tid * chunk;
    int end = min(beg + chunk, n);

    int s = 0;
    for (int i = beg; i < end; i++) s += cnt[i];

    // block-wide exclusive scan of s
    __shared__ int warpsum[32];
    int lane = tid & 31, wid = tid >> 5;
    int v = s;
#pragma unroll
    for (int o = 1; o < 32; o <<= 1) {
        int t = __shfl_up_sync(0xffffffffu, v, o);
        if (lane >= o) v += t;
    }
    if (lane == 31) warpsum[wid] = v;
    __syncthreads();
    if (wid == 0) {
        int w = warpsum[lane];
#pragma unroll
        for (int o = 1; o < 32; o <<= 1) {
            int t = __shfl_up_sync(0xffffffffu, w, o);
            if (lane >= o) w += t;
        }
        warpsum[lane] = w;
    }
    __syncthreads();
    int run = v - s + (wid > 0 ? warpsum[wid - 1] : 0);   // exclusive prefix

    for (int i = beg; i < end; i++) {
        rp[i] = run;
        run += cnt[i];
    }
    if (beg < n && end == n) rp[n] = run;
}

__global__ void k_cursor() {
    int i = blockIdx.x * blockDim.x + threadIdx.x;
    if (i <= NG) d_cur_ug[i] = d_rp_ug[i];
    if (i <= NU) d_cur_gu[i] = d_rp_gu[i];
}

__global__ void k_scatter(const int* __restrict__ sug, const int* __restrict__ dug,
                          const float* __restrict__ wug,
                          const int* __restrict__ sgu, const int* __restrict__ dgu,
                          const float* __restrict__ wgu) {
    int e = blockIdx.x * blockDim.x + threadIdx.x;
    if (e < NE) {
        int p = atomicAdd(&d_cur_ug[dug[e]], 1);
        d_es_ug[p] = sug[e];
        d_ws_ug[p] = wug[e];
        int q = atomicAdd(&d_cur_gu[dgu[e]], 1);
        d_es_gu[q] = sgu[e];
        d_ws_gu[q] = wgu[e];
    }
}

// ----------------------------------------------------------------------------
// Segment sum by CSR rows: out[row,:] = sum_j w_j * X[src_j,:]
// Block = 128 threads, one row per block. D=256 uses float2 lanes.
// ----------------------------------------------------------------------------
__global__ void k_segsum256(const float* __restrict__ X,
                            const int* __restrict__ rp,
                            const int* __restrict__ es,
                            const float* __restrict__ wv,
                            float* __restrict__ out) {
    constexpr int T = 128;
    int row = blockIdx.x;
    int beg = rp[row], end = rp[row + 1];
    int tid = threadIdx.x;

    float2 acc = make_float2(0.f, 0.f);
    __shared__ int   ss[T];
    __shared__ float sw[T];

    for (int base = beg; base < end; base += T) {
        int cnt = min(T, end - base);
        if (tid < cnt) { ss[tid] = es[base + tid]; sw[tid] = wv[base + tid]; }
        __syncthreads();
#pragma unroll 4
        for (int j = 0; j < cnt; j++) {
            const float2* xr = (const float2*)(X + (size_t)ss[j] * 256);
            float wj = sw[j];
            float2 x = xr[tid];
            acc.x += wj * x.x;
            acc.y += wj * x.y;
        }
        __syncthreads();
    }
    ((float2*)(out + (size_t)row * 256))[tid] = acc;
}

__global__ void k_segsum128(const float* __restrict__ X,
                            const int* __restrict__ rp,
                            const int* __restrict__ es,
                            const float* __restrict__ wv,
                            float* __restrict__ out) {
    constexpr int T = 128;
    int row = blockIdx.x;
    int beg = rp[row], end = rp[row + 1];
    int tid = threadIdx.x;

    float acc = 0.f;
    __shared__ int   ss[T];
    __shared__ float sw[T];

    for (int base = beg; base < end; base += T) {
        int cnt = min(T, end - base);
        if (tid < cnt) { ss[tid] = es[base + tid]; sw[tid] = wv[base + tid]; }
        __syncthreads();
#pragma unroll 4
        for (int j = 0; j < cnt; j++) {
            acc += sw[j] * X[(size_t)ss[j] * 128 + tid];
        }
        __syncthreads();
    }
    out[(size_t)row * 128 + tid] = acc;
}

// ----------------------------------------------------------------------------
// Fused SGEMM: C[M,256] = relu?( A1@W1 + (A2@W2)? + pre? + bias? )
// 128x128x16 tile, double-buffered smem, 256 threads, 8x8 microtile.
// N fixed at 256, grid.y = 2. K1/K2 must be multiples of 16.
// ----------------------------------------------------------------------------
__global__ __launch_bounds__(256)
void k_gemm(const float* __restrict__ A1, const float* __restrict__ W1, int K1,
            const float* __restrict__ A2, const float* __restrict__ W2, int K2,
            const float* __restrict__ pre, const float* __restrict__ bias,
            float* __restrict__ C, int M, int relu) {
    constexpr int BM = 128, BN = 128, BK = 16;
    __shared__ float As[2][BK][BM + 4];
    __shared__ float Bs[2][BK][BN];

    int tid = threadIdx.x;
    int tx = tid & 15;        // 0..15  (cols)
    int ty = tid >> 4;        // 0..15  (rows)
    int brow = blockIdx.x * BM;
    int bcol = blockIdx.y * BN;

    float acc[8][8];
#pragma unroll
    for (int i = 0; i < 8; i++)
#pragma unroll
        for (int j = 0; j < 8; j++) acc[i][j] = 0.f;

    // A tile loader: 128x16 = 512 float4s; this thread loads rows ar, ar+64
    int ar  = tid >> 2;            // 0..63
    int ac4 = (tid & 3) * 4;       // 0,4,8,12
    int gr0 = brow + ar, gr1 = brow + ar + 64;
    bool av0 = (gr0 < M), av1 = (gr1 < M);
    int cr0 = av0 ? gr0 : (M - 1);
    int cr1 = av1 ? gr1 : (M - 1);
    // W tile loader: 16x128 = 512 float4s; rows wr, wr+8
    int wr  = tid >> 5;            // 0..7
    int wc4 = (tid & 31) * 4;      // 0..124

    const float4 f4z = make_float4(0.f, 0.f, 0.f, 0.f);

    for (int pass = 0; pass < 2; pass++) {
        const float* A = pass ? A2 : A1;
        const float* W = pass ? W2 : W1;
        int K = pass ? K2 : K1;
        if (A == nullptr) continue;
        const float* Ap0 = A + (size_t)cr0 * K;
        const float* Ap1 = A + (size_t)cr1 * K;

        // guard: previous pass's last compute must finish before reuse of buffers
        __syncthreads();

        // preload tile k0=0 into buffer 0
        {
            float4 a0 = av0 ? *(const float4*)(Ap0 + ac4) : f4z;
            float4 a1 = av1 ? *(const float4*)(Ap1 + ac4) : f4z;
            float4 w0 = *(const float4*)(W + (size_t)wr * 256 + bcol + wc4);
            float4 w1 = *(const float4*)(W + (size_t)(wr + 8) * 256 + bcol + wc4);
            As[0][ac4 + 0][ar] = a0.x; As[0][ac4 + 1][ar] = a0.y;
            As[0][ac4 + 2][ar] = a0.z; As[0][ac4 + 3][ar] = a0.w;
            As[0][ac4 + 0][ar + 64] = a1.x; As[0][ac4 + 1][ar + 64] = a1.y;
            As[0][ac4 + 2][ar + 64] = a1.z; As[0][ac4 + 3][ar + 64] = a1.w;
            *(float4*)&Bs[0][wr][wc4] = w0;
            *(float4*)&Bs[0][wr + 8][wc4] = w1;
        }
        __syncthreads();

        int buf = 0;
        for (int k0 = 0; k0 < K; k0 += BK) {
            bool more = (k0 + BK) < K;
            float4 na0, na1, nw0, nw1;
            if (more) {
                int kn = k0 + BK;
                na0 = av0 ? *(const float4*)(Ap0 + kn + ac4) : f4z;
                na1 = av1 ? *(const float4*)(Ap1 + kn + ac4) : f4z;
                nw0 = *(const float4*)(W + (size_t)(kn + wr) * 256 + bcol + wc4);
                nw1 = *(const float4*)(W + (size_t)(kn + wr + 8) * 256 + bcol + wc4);
            }
#pragma unroll
            for (int k = 0; k < BK; k++) {
                float ra[8], rb[8];
#pragma unroll
                for (int i = 0; i < 8; i++) ra[i] = As[buf][k][ty * 8 + i];
#pragma unroll
                for (int j = 0; j < 8; j++) rb[j] = Bs[buf][k][tx * 8 + j];
#pragma unroll
                for (int i = 0; i < 8; i++)
#pragma unroll
                    for (int j = 0; j < 8; j++) acc[i][j] += ra[i] * rb[j];
            }
            if (more) {
                int nb = buf ^ 1;
                As[nb][ac4 + 0][ar] = na0.x; As[nb][ac4 + 1][ar] = na0.y;
                As[nb][ac4 + 2][ar] = na0.z; As[nb][ac4 + 3][ar] = na0.w;
                As[nb][ac4 + 0][ar + 64] = na1.x; As[nb][ac4 + 1][ar + 64] = na1.y;
                As[nb][ac4 + 2][ar + 64] = na1.z; As[nb][ac4 + 3][ar + 64] = na1.w;
                *(float4*)&Bs[nb][wr][wc4] = nw0;
                *(float4*)&Bs[nb][wr + 8][wc4] = nw1;
                __syncthreads();
            }
            buf ^= 1;
        }
    }

    // Epilogue
    float bb[8];
#pragma unroll
    for (int j = 0; j < 8; j++) bb[j] = bias ? bias[bcol + tx * 8 + j] : 0.f;

#pragma unroll
    for (int i = 0; i < 8; i++) {
        int r = brow + ty * 8 + i;
        if (r >= M) continue;
        size_t off = (size_t)r * 256 + bcol + tx * 8;
#pragma unroll
        for (int j = 0; j < 8; j++) {
            float v = acc[i][j] + bb[j];
            if (pre) v += pre[off + j];
            if (relu) v = fmaxf(v, 0.f);
            C[off + j] = v;
        }
    }
}

// ----------------------------------------------------------------------------
// Decoder: out[s] = dot(u[row[s]], g[col[s]]) over 256 dims. One warp per s.
// ----------------------------------------------------------------------------
__global__ void k_decode(const float* __restrict__ u, const float* __restrict__ g,
                         const int* __restrict__ rows, const int* __restrict__ cols,
                         float* __restrict__ out) {
    int w = (blockIdx.x * blockDim.x + threadIdx.x) >> 5;
    int lane = threadIdx.x & 31;
    if (w >= NS) return;
    const float4* ur = (const float4*)(u + (size_t)rows[w] * 256);
    const float4* gr = (const float4*)(g + (size_t)cols[w] * 256);
    float acc = 0.f;
#pragma unroll
    for (int i = 0; i < 2; i++) {
        float4 a = ur[lane + i * 32];
        float4 b = gr[lane + i * 32];
        acc += a.x * b.x + a.y * b.y + a.z * b.z + a.w * b.w;
    }
#pragma unroll
    for (int o = 16; o; o >>= 1) acc += __shfl_down_sync(0xffffffffu, acc, o);
    if (lane == 0) out[w] = acc;
}

// ----------------------------------------------------------------------------
// Host side
// ----------------------------------------------------------------------------
static void run_layer(const float* u_prev, int du, const float* g_prev, int dg,
                      const float* Wr_ug, const float* b_ug, const float* Wo_g,
                      const float* Wr_gu, const float* b_gu, const float* Wo_u,
                      float* g_out, float* u_out, int relu,
                      float* p_msg_g, float* p_y, float* p_msg_u,
                      int* p_rp_ug, int* p_es_ug, float* p_ws_ug,
                      int* p_rp_gu, int* p_es_gu, float* p_ws_gu) {
    // users -> games (direct form): msg_g[NG,du] = segsum_ug(u_prev)
    if (du == 128)
        k_segsum128<<<NG, 128>>>(u_prev, p_rp_ug, p_es_ug, p_ws_ug, p_msg_g);
    else
        k_segsum256<<<NG, 128>>>(u_prev, p_rp_ug, p_es_ug, p_ws_ug, p_msg_g);
    // g_out = relu?(msg_g@Wr_ug + g_prev@Wo_g + b_ug)
    k_gemm<<<dim3((NG + 127) / 128, 2), 256>>>(p_msg_g, Wr_ug, du,
                                               g_prev, Wo_g, dg,
                                               nullptr, b_ug, g_out, NG, relu);
    // games -> users (commuted form): y = g_prev@Wr_gu  [NG,256]
    k_gemm<<<dim3((NG + 127) / 128, 2), 256>>>(g_prev, Wr_gu, dg,
                                               nullptr, nullptr, 0,
                                               nullptr, nullptr, p_y, NG, 0);
    // msg_u[NU,256] = segsum_gu(y)
    k_segsum256<<<NU, 128>>>(p_y, p_rp_gu, p_es_gu, p_ws_gu, p_msg_u);
    // u_out = relu?(msg_u + u_prev@Wo_u + b_gu)
    k_gemm<<<dim3((NU + 127) / 128, 2), 256>>>(u_prev, Wo_u, du,
                                               nullptr, nullptr, 0,
                                               p_msg_u, b_gu, u_out, NU, relu);
}

extern "C" void kernel_launch(void* const* d_in, const int* in_sizes, int n_in,
                              void* d_out, int out_size) {
    // ---- input mapping (handles both metadata orderings) ----
    const float *x_user, *x_game, *emb_game, *ew_ug, *ew_gu;
    const int *src_ug, *dst_ug, *src_gu, *dst_gu, *srow, *scol;
    const float *Wrug[3], *bug[3], *Wog[3], *Wrgu[3], *bgu[3], *Wou[3];

    x_user   = (const float*)d_in[0];
    x_game   = (const float*)d_in[1];
    emb_game = (const float*)d_in[2];
    ew_ug    = (const float*)d_in[3];
    ew_gu    = (const float*)d_in[4];

    if (in_sizes[5] == NE) {
        // setup_inputs dict order
        src_ug = (const int*)d_in[5];
        dst_ug = (const int*)d_in[6];
        src_gu = (const int*)d_in[7];
        dst_gu = (const int*)d_in[8];
        srow   = (const int*)d_in[9];
        scol   = (const int*)d_in[10];
        for (int l = 0; l < 3; l++) {
            int b = 11 + 6 * l;
            Wrug[l] = (const float*)d_in[b + 0];
            bug[l]  = (const float*)d_in[b + 1];
            Wog[l]  = (const float*)d_in[b + 2];
            Wrgu[l] = (const float*)d_in[b + 3];
            bgu[l]  = (const float*)d_in[b + 4];
            Wou[l]  = (const float*)d_in[b + 5];
        }
    } else {
        // reference signature order
        for (int l = 0; l < 3; l++) {
            int b = 5 + 6 * l;
            Wrug[l] = (const float*)d_in[b + 0];
            bug[l]  = (const float*)d_in[b + 1];
            Wog[l]  = (const float*)d_in[b + 2];
            Wrgu[l] = (const float*)d_in[b + 3];
            bgu[l]  = (const float*)d_in[b + 4];
            Wou[l]  = (const float*)d_in[b + 5];
        }
        src_ug = (const int*)d_in[23];
        dst_ug = (const int*)d_in[24];
        src_gu = (const int*)d_in[25];
        dst_gu = (const int*)d_in[26];
        srow   = (const int*)d_in[27];
        scol   = (const int*)d_in[28];
    }

    // ---- scratch symbol addresses ----
    float *p_xg, *p_u0, *p_u1, *p_g0, *p_g1, *p_msg_g, *p_y, *p_msg_u;
    float *p_ws_ug, *p_ws_gu;
    int *p_rp_ug, *p_rp_gu, *p_es_ug, *p_es_gu;
    cudaGetSymbolAddress((void**)&p_xg, d_xg);
    cudaGetSymbolAddress((void**)&p_u0, d_u0);
    cudaGetSymbolAddress((void**)&p_u1, d_u1);
    cudaGetSymbolAddress((void**)&p_g0, d_g0);
    cudaGetSymbolAddress((void**)&p_g1, d_g1);
    cudaGetSymbolAddress((void**)&p_msg_g, d_msg_g);
    cudaGetSymbolAddress((void**)&p_y, d_y);
    cudaGetSymbolAddress((void**)&p_msg_u, d_msg_u);
    cudaGetSymbolAddress((void**)&p_rp_ug, d_rp_ug);
    cudaGetSymbolAddress((void**)&p_rp_gu, d_rp_gu);
    cudaGetSymbolAddress((void**)&p_es_ug, d_es_ug);
    cudaGetSymbolAddress((void**)&p_es_gu, d_es_gu);
    cudaGetSymbolAddress((void**)&p_ws_ug, d_ws_ug);
    cudaGetSymbolAddress((void**)&p_ws_gu, d_ws_gu);

    float* out = (float*)d_out;

    // ---- setup: concat game features, build CSR (both directions) ----
    k_concat<<<(NG * 64 + 255) / 256, 256>>>(x_game, emb_game);
    k_zero_counts<<<(NU + 256) / 256, 256>>>();
    k_hist<<<(NE + 255) / 256, 256>>>(dst_ug, dst_gu);
    k_scan<<<2, 1024>>>();
    k_cursor<<<(NU + 256) / 256, 256>>>();
    k_scatter<<<(NE + 255) / 256, 256>>>(src_ug, dst_ug, ew_ug,
                                         src_gu, dst_gu, ew_gu);

    // ---- 3 GraphConv layers ----
    run_layer(x_user, 128, p_xg, 128,
              Wrug[0], bug[0], Wog[0], Wrgu[0], bgu[0], Wou[0],
              p_g0, p_u0, 1,
              p_msg_g, p_y, p_msg_u,
              p_rp_ug, p_es_ug, p_ws_ug, p_rp_gu, p_es_gu, p_ws_gu);
    run_layer(p_u0, 256, p_g0, 256,
              Wrug[1], bug[1], Wog[1], Wrgu[1], bgu[1], Wou[1],
              p_g1, p_u1, 1,
              p_msg_g, p_y, p_msg_u,
              p_rp_ug, p_es_ug, p_ws_ug, p_rp_gu, p_es_gu, p_ws_gu);
    run_layer(p_u1, 256, p_g1, 256,
              Wrug[2], bug[2], Wog[2], Wrgu[2], bgu[2], Wou[2],
              p_g0, p_u0, 0,
              p_msg_g, p_y, p_msg_u,
              p_rp_ug, p_es_ug, p_ws_ug, p_rp_gu, p_es_gu, p_ws_gu);

    // ---- decoder ----
    k_decode<<<(NS * 32 + 255) / 256, 256>>>(p_u0, p_g0, srow, scol, out);
    (void)n_in; (void)out_size;
}